// round 7
// baseline (speedup 1.0000x reference)
#include <cuda_runtime.h>
#include <math.h>
#include <stdint.h>

// Problem constants
#define BATCH 8
#define CIN   256
#define NSEQ  4096
#define DKQ   64
#define DOUT  256

// Attention tiling
#define BM 64    // query rows per CTA (4 warps x 16)
#define BK 64    // key rows per tile
#define NTILES (NSEQ / BK)

// Scratch (device globals)
__device__ float g_q[(size_t)BATCH * NSEQ * DKQ];   // [b][n][64], full fp32, scaled log2e/8
__device__ float g_k[(size_t)BATCH * NSEQ * DKQ];   // [b][n][64], full fp32
__device__ float g_v[(size_t)BATCH * NSEQ * DOUT];  // [b][n][256], tf32-truncated

__device__ __forceinline__ float tf32_hi(float x) {
    return __uint_as_float(__float_as_uint(x) & 0xFFFFE000u);
}
__device__ __forceinline__ float fast_exp2(float x) {
    float r;
    asm("ex2.approx.ftz.f32 %0, %1;" : "=f"(r) : "f"(x));
    return r;
}

// packed f32x2 helpers for projection
__device__ __forceinline__ unsigned long long pack2(float a, float b) {
    unsigned long long r;
    asm("mov.b64 %0, {%1, %2};" : "=l"(r) : "f"(a), "f"(b));
    return r;
}
__device__ __forceinline__ void ffma2(unsigned long long& acc,
                                      unsigned long long a, unsigned long long b) {
    asm("fma.rn.f32x2 %0, %1, %2, %3;" : "=l"(acc) : "l"(a), "l"(b), "l"(acc));
}
__device__ __forceinline__ float2 unpack2(unsigned long long v) {
    float2 r;
    asm("mov.b64 {%0, %1}, %2;" : "=f"(r.x), "=f"(r.y) : "l"(v));
    return r;
}

// m16n8k8 tf32 mma: D += A x B (row.col), accum fp32
__device__ __forceinline__ void mma8(float4& d,
                                     uint32_t a0, uint32_t a1, uint32_t a2, uint32_t a3,
                                     uint32_t b0, uint32_t b1) {
    asm("mma.sync.aligned.m16n8k8.row.col.f32.tf32.tf32.f32 "
        "{%0,%1,%2,%3}, {%4,%5,%6,%7}, {%8,%9}, {%0,%1,%2,%3};"
        : "+f"(d.x), "+f"(d.y), "+f"(d.z), "+f"(d.w)
        : "r"(a0), "r"(a1), "r"(a2), "r"(a3), "r"(b0), "r"(b1));
}

// ==================== projection kernel ====================
__global__ __launch_bounds__(256) void proj_kernel(const float* __restrict__ x,
                                                   const float* __restrict__ Wq,
                                                   const float* __restrict__ Wk,
                                                   const float* __restrict__ Wv) {
    const int n0    = blockIdx.x * 64;
    const int jtile = blockIdx.y;      // 0:q  1:k  2..5:v chunks
    const int b     = blockIdx.z;

    const float* W;
    int j0;
    float scale;
    if (jtile == 0)      { W = Wq; j0 = 0;            scale = 0.125f * 1.4426950408889634f; }
    else if (jtile == 1) { W = Wk; j0 = 0;            scale = 1.0f; }
    else                 { W = Wv; j0 = (jtile-2)*64; scale = 1.0f; }

    __shared__ float xs[16][64];
    __shared__ float wt[16][64];

    const int t  = threadIdx.x;
    const int tn = t >> 4;
    const int tj = t & 15;

    unsigned long long acc2[4][2];
    #pragma unroll
    for (int i = 0; i < 4; i++) { acc2[i][0] = 0ull; acc2[i][1] = 0ull; }

    for (int c0 = 0; c0 < CIN; c0 += 16) {
        {
            int cc = t >> 4;
            int nn = (t & 15) * 4;
            float4 xv = *(const float4*)&x[((size_t)(b * CIN + c0 + cc)) * NSEQ + n0 + nn];
            *(float4*)&xs[cc][nn] = xv;
        }
        {
            int jj = t >> 2;
            int cp = (t & 3) * 4;
            float4 wv = *(const float4*)&W[(size_t)(j0 + jj) * CIN + c0 + cp];
            wt[cp + 0][jj] = wv.x;
            wt[cp + 1][jj] = wv.y;
            wt[cp + 2][jj] = wv.z;
            wt[cp + 3][jj] = wv.w;
        }
        __syncthreads();
        #pragma unroll
        for (int c = 0; c < 16; c++) {
            ulonglong2 b2 = *(const ulonglong2*)&wt[c][4 * tj];
            #pragma unroll
            for (int i = 0; i < 4; i++) {
                float a = xs[c][4 * tn + i];
                unsigned long long aa = pack2(a, a);
                ffma2(acc2[i][0], aa, b2.x);
                ffma2(acc2[i][1], aa, b2.y);
            }
        }
        __syncthreads();
    }

    float* outp = (jtile == 0) ? g_q : (jtile == 1) ? g_k : g_v;
    int odim = (jtile >= 2) ? DOUT : DKQ;
    bool trunc = (jtile >= 2);   // only V tf32-truncated at rest; q/k split in attn
    #pragma unroll
    for (int i = 0; i < 4; i++) {
        int n = n0 + 4 * tn + i;
        size_t base = ((size_t)b * NSEQ + n) * odim + j0 + 4 * tj;
        float2 lo = unpack2(acc2[i][0]);
        float2 hi = unpack2(acc2[i][1]);
        float4 v = make_float4(lo.x * scale, lo.y * scale, hi.x * scale, hi.y * scale);
        if (trunc) v = make_float4(tf32_hi(v.x), tf32_hi(v.y), tf32_hi(v.z), tf32_hi(v.w));
        *(float4*)&outp[base] = v;
    }
}

// ==================== mma.sync flash attention ====================
// 128 threads = 4 warps x 16 query rows. 2 CTAs per SM.
// sKh/sKl [64][72]: col c at (c&3)*2 + ((c>>2)&1) + (c>>3)*8  -> B frags via LDS.64
// sV [32][264]: half-tile (128 n); k rows paired (k,k+4), n-pairs interleaved
// sP [64][68]: plain row-major (also Q staging in prologue)
#define KH_O 0        // 64*72 = 4608
#define KL_O 4608     // 4608
#define V_O  9216     // 32*264 = 8448
#define P_O  17664    // 64*68 = 4352
#define SMEM_FLOATS 22016   // 88064 bytes

__global__ __launch_bounds__(128, 2) void attn_mma(float* __restrict__ out) {
    extern __shared__ float sm[];
    float* sKh = sm + KH_O;
    float* sKl = sm + KL_O;
    float* sV  = sm + V_O;
    float* sP  = sm + P_O;
    const uint32_t* sPu = (const uint32_t*)sP;

    const int tid = threadIdx.x;
    const int w   = tid >> 5;
    const int ln  = tid & 31;
    const int l4  = ln >> 2;   // 0..7
    const int lm4 = ln & 3;    // 0..3
    const int b   = blockIdx.y;
    const int n0  = blockIdx.x * BM;

    // ---- stage Q through sP, build per-lane Qh/Ql fragments in registers ----
    uint32_t qh0[8], qh1[8], qh2[8], qh3[8];
    uint32_t ql0[8], ql1[8], ql2[8], ql3[8];
    {
        const float* qg = g_q + ((size_t)b * NSEQ + n0) * DKQ;
        #pragma unroll
        for (int it = 0; it < 8; it++) {
            int i = tid + it * 128;         // 1024 tasks: 64 rows x 16 f4
            int r = i >> 4, c4 = i & 15;
            *(float4*)&sP[r * 68 + 4 * c4] = *(const float4*)&qg[(size_t)r * DKQ + 4 * c4];
        }
        __syncthreads();
        const int r0 = (w * 16 + l4) * 68;
        const int r1 = r0 + 8 * 68;
        #pragma unroll
        for (int kt = 0; kt < 8; kt++) {
            int c0 = kt * 8 + lm4;
            float v00 = sP[r0 + c0],     v10 = sP[r1 + c0];
            float v01 = sP[r0 + c0 + 4], v11 = sP[r1 + c0 + 4];
            float h00 = tf32_hi(v00), h10 = tf32_hi(v10);
            float h01 = tf32_hi(v01), h11 = tf32_hi(v11);
            qh0[kt] = __float_as_uint(h00); qh1[kt] = __float_as_uint(h10);
            qh2[kt] = __float_as_uint(h01); qh3[kt] = __float_as_uint(h11);
            ql0[kt] = __float_as_uint(tf32_hi(v00 - h00));
            ql1[kt] = __float_as_uint(tf32_hi(v10 - h10));
            ql2[kt] = __float_as_uint(tf32_hi(v01 - h01));
            ql3[kt] = __float_as_uint(tf32_hi(v11 - h11));
        }
    }

    float4 O[32];
    #pragma unroll
    for (int nt = 0; nt < 32; nt++) O[nt] = make_float4(0.f, 0.f, 0.f, 0.f);
    float lsumA = 0.f, lsumB = 0.f;

    const int arow68 = (w * 16 + l4) * 68;

    #pragma unroll 1
    for (int t = 0; t < NTILES; t++) {
        const int k0 = t * BK;
        __syncthreads();   // prev-tile readers of sK / sV(half1) done

        // ---- load K tile (hi/lo split, col-pair interleaved) ----
        {
            const float* kg = g_k + ((size_t)b * NSEQ + k0) * DKQ;
            #pragma unroll
            for (int it = 0; it < 4; it++) {
                int i = tid + it * 128;     // 512 tasks: 64 rows x 8 col-groups
                int r = i >> 3, g = i & 7;
                float4 F = *(const float4*)&kg[(size_t)r * DKQ + g * 8];
                float4 G = *(const float4*)&kg[(size_t)r * DKQ + g * 8 + 4];
                float4 Fh = make_float4(tf32_hi(F.x), tf32_hi(F.y), tf32_hi(F.z), tf32_hi(F.w));
                float4 Gh = make_float4(tf32_hi(G.x), tf32_hi(G.y), tf32_hi(G.z), tf32_hi(G.w));
                float4 Fl = make_float4(F.x - Fh.x, F.y - Fh.y, F.z - Fh.z, F.w - Fh.w);
                float4 Gl = make_float4(G.x - Gh.x, G.y - Gh.y, G.z - Gh.z, G.w - Gh.w);
                *(float4*)&sKh[r * 72 + g * 8]     = make_float4(Fh.x, Gh.x, Fh.y, Gh.y);
                *(float4*)&sKh[r * 72 + g * 8 + 4] = make_float4(Fh.z, Gh.z, Fh.w, Gh.w);
                *(float4*)&sKl[r * 72 + g * 8]     = make_float4(Fl.x, Gl.x, Fl.y, Gl.y);
                *(float4*)&sKl[r * 72 + g * 8 + 4] = make_float4(Fl.z, Gl.z, Fl.w, Gl.w);
            }
        }
        // ---- load V half 0 (n channels 0..127) ----
        {
            const float* vg = g_v + ((size_t)b * NSEQ + k0) * DOUT;
            #pragma unroll
            for (int it = 0; it < 16; it++) {
                int i = tid + it * 128;     // 2048 tasks: 32 row-pairs x 64 n-pairs
                int np = i & 63, rp = i >> 6;
                int k = ((rp >> 2) << 3) + (rp & 3);
                float2 A = *(const float2*)&vg[(size_t)k * DOUT + 2 * np];
                float2 B = *(const float2*)&vg[(size_t)(k + 4) * DOUT + 2 * np];
                *(float4*)&sV[rp * 264 + 4 * np] = make_float4(A.x, B.x, A.y, B.y);
            }
        }
        __syncthreads();

        // ---- S = Qhi*(Khi+Klo) + Qlo*Khi  (3-pass tf32) ----
        float4 S[8];
        #pragma unroll
        for (int nt = 0; nt < 8; nt++) S[nt] = make_float4(0.f, 0.f, 0.f, 0.f);

        #pragma unroll
        for (int kt = 0; kt < 8; kt++) {
            #pragma unroll
            for (int nt = 0; nt < 8; nt++) {
                const int bc = (nt * 8 + l4) * 72 + kt * 8 + lm4 * 2;
                float2 kh = *(const float2*)&sKh[bc];
                float2 kl = *(const float2*)&sKl[bc];
                uint32_t khx = __float_as_uint(kh.x), khy = __float_as_uint(kh.y);
                mma8(S[nt], qh0[kt], qh1[kt], qh2[kt], qh3[kt], khx, khy);
                mma8(S[nt], qh0[kt], qh1[kt], qh2[kt], qh3[kt],
                     __float_as_uint(kl.x), __float_as_uint(kl.y));
                mma8(S[nt], ql0[kt], ql1[kt], ql2[kt], ql3[kt], khx, khy);
            }
        }

        // ---- softmax (no max subtraction; s pre-scaled to log2 domain) ----
        #pragma unroll
        for (int nt = 0; nt < 8; nt++) {
            float p0 = tf32_hi(fast_exp2(S[nt].x));
            float p1 = tf32_hi(fast_exp2(S[nt].y));
            float p2 = tf32_hi(fast_exp2(S[nt].z));
            float p3 = tf32_hi(fast_exp2(S[nt].w));
            lsumA += p0 + p1;
            lsumB += p2 + p3;
            const int pc = arow68 + nt * 8 + 2 * lm4;
            *(float2*)&sP[pc]          = make_float2(p0, p1);
            *(float2*)&sP[pc + 8 * 68] = make_float2(p2, p3);
        }
        __syncwarp();   // P rows are warp-private

        // ---- O += P * V : half 0 ----
        #pragma unroll 1
        for (int kt = 0; kt < 8; kt++) {
            const int ac = arow68 + kt * 8 + lm4;
            uint32_t p0 = sPu[ac],     p1 = sPu[ac + 8 * 68];
            uint32_t p2 = sPu[ac + 4], p3 = sPu[ac + 8 * 68 + 4];
            const int vb = (kt * 4 + lm4) * 264 + l4 * 2;
            #pragma unroll
            for (int nt = 0; nt < 16; nt++) {
                float2 v2 = *(const float2*)&sV[vb + nt * 16];
                mma8(O[nt], p0, p1, p2, p3,
                     __float_as_uint(v2.x), __float_as_uint(v2.y));
            }
        }
        __syncthreads();   // all warps done reading V half 0

        // ---- load V half 1 (n channels 128..255) ----
        {
            const float* vg = g_v + ((size_t)b * NSEQ + k0) * DOUT + 128;
            #pragma unroll
            for (int it = 0; it < 16; it++) {
                int i = tid + it * 128;
                int np = i & 63, rp = i >> 6;
                int k = ((rp >> 2) << 3) + (rp & 3);
                float2 A = *(const float2*)&vg[(size_t)k * DOUT + 2 * np];
                float2 B = *(const float2*)&vg[(size_t)(k + 4) * DOUT + 2 * np];
                *(float4*)&sV[rp * 264 + 4 * np] = make_float4(A.x, B.x, A.y, B.y);
            }
        }
        __syncthreads();

        // ---- O += P * V : half 1 ----
        #pragma unroll 1
        for (int kt = 0; kt < 8; kt++) {
            const int ac = arow68 + kt * 8 + lm4;
            uint32_t p0 = sPu[ac],     p1 = sPu[ac + 8 * 68];
            uint32_t p2 = sPu[ac + 4], p3 = sPu[ac + 8 * 68 + 4];
            const int vb = (kt * 4 + lm4) * 264 + l4 * 2;
            #pragma unroll
            for (int nt = 0; nt < 16; nt++) {
                float2 v2 = *(const float2*)&sV[vb + nt * 16];
                mma8(O[16 + nt], p0, p1, p2, p3,
                     __float_as_uint(v2.x), __float_as_uint(v2.y));
            }
        }
    }

    // ---- epilogue ----
    lsumA += __shfl_xor_sync(0xffffffffu, lsumA, 1);
    lsumA += __shfl_xor_sync(0xffffffffu, lsumA, 2);
    lsumB += __shfl_xor_sync(0xffffffffu, lsumB, 1);
    lsumB += __shfl_xor_sync(0xffffffffu, lsumB, 2);
    float invA = 1.0f / lsumA;
    float invB = 1.0f / lsumB;

    const int n = n0 + w * 16 + l4;
    float* ob = out + (size_t)b * DOUT * NSEQ + n;
    #pragma unroll
    for (int nt = 0; nt < 32; nt++) {
        int o = nt * 8 + 2 * lm4;
        ob[(size_t)o * NSEQ]           = O[nt].x * invA;
        ob[(size_t)(o + 1) * NSEQ]     = O[nt].y * invA;
        ob[(size_t)o * NSEQ + 8]       = O[nt].z * invB;
        ob[(size_t)(o + 1) * NSEQ + 8] = O[nt].w * invB;
    }
}

extern "C" void kernel_launch(void* const* d_in, const int* in_sizes, int n_in,
                              void* d_out, int out_size) {
    (void)in_sizes; (void)n_in; (void)out_size;
    const float* x  = (const float*)d_in[0];
    const float* Wq = (const float*)d_in[1];
    const float* Wk = (const float*)d_in[2];
    const float* Wv = (const float*)d_in[3];
    float* out = (float*)d_out;

    cudaFuncSetAttribute(attn_mma, cudaFuncAttributeMaxDynamicSharedMemorySize,
                         SMEM_FLOATS * (int)sizeof(float));

    dim3 gp(NSEQ / 64, 6, BATCH);
    proj_kernel<<<gp, 256>>>(x, Wq, Wk, Wv);

    dim3 ga(NSEQ / BM, BATCH);
    attn_mma<<<ga, 128, SMEM_FLOATS * sizeof(float)>>>(out);
}